// round 10
// baseline (speedup 1.0000x reference)
#include <cuda_runtime.h>
#include <math.h>

#define B_   8
#define T_   64
#define CIN_ 64
#define L_   256
#define F_   128
#define CO_  512   // 4*F

// Scratch (device globals — no runtime allocation allowed).
__device__ float g_Ax[(size_t)512 * CO_ * L_];
__device__ float g_hs0[(size_t)T_ * B_ * F_ * L_];
__device__ float g_c0s[(size_t)B_ * F_ * L_];
__device__ float g_c1s[(size_t)B_ * F_ * L_];
__device__ int   g_bcnt[B_];   // per-batch step counters (zeroed before each persistent launch)

__device__ __forceinline__ float sigm(float x) { return 1.0f / (1.0f + __expf(-x)); }
__device__ __forceinline__ float tanh_fast(float x) { return 2.0f / (1.0f + __expf(-2.0f * x)) - 1.0f; }

__device__ __forceinline__ unsigned long long bcast2(float v) {
    unsigned long long r;
    asm("mov.b64 %0, {%1, %1};" : "=l"(r) : "f"(v));
    return r;
}
__device__ __forceinline__ float2 unpack2(unsigned long long p) {
    float2 r;
    asm("mov.b64 {%0, %1}, %2;" : "=f"(r.x), "=f"(r.y) : "l"(p));
    return r;
}
#define FMA2(acc, w, x) \
    asm("fma.rn.f32x2 %0, %1, %2, %0;" : "+l"(acc) : "l"(w), "l"(x))

extern __shared__ char dynsmem[];
#define CONV_SMEM (2*80*16*16 + 2*16*136*4)           // 58368 B
#define SEQ_SMEM  (2560*16 + 2*16*264*4)              // 40960 + 33792 = 74752 B

// ---------------------------------------------------------------------------
// Parallel precompute conv (unchanged — measured ~99% of FMA2 roofline).
// ---------------------------------------------------------------------------
__global__ __launch_bounds__(256, 2) void conv_gemm_kernel(
    const float* __restrict__ X,     // [NB, Cx, L]
    const float* __restrict__ W,     // [CO, CW, 5]
    const float* __restrict__ bias,  // [CO]
    float* __restrict__ out,         // [NB, CO, L]
    int Cx, int CW, int c0w)
{
    float4* Wsm = (float4*)dynsmem;                              // [2][80][16]
    float*  Xsm = (float*)(dynsmem + 2*80*16*sizeof(float4));    // [2][16][136]

    const int tid = threadIdx.x;
    const int tx = tid & 15, ty = tid >> 4;
    const int l0  = blockIdx.x * 128;
    const int co0 = blockIdx.y * 64;
    const int n   = blockIdx.z;
    const float* Xn = X + (size_t)n * Cx * L_;

    const int wRow = tid >> 2, wPart = tid & 3;
    const int nCh = Cx >> 4;

    unsigned long long accp[2][8];
    #pragma unroll
    for (int p = 0; p < 2; p++)
        #pragma unroll
        for (int j = 0; j < 8; j++) accp[p][j] = 0ULL;

    float4 wv[5];
    float  xv[9];

    auto ldW = [&](int ch) {
        const float4* wp = (const float4*)(W + (size_t)(co0 + wRow) * CW * 5
                                             + (size_t)(c0w + (ch << 4)) * 5 + wPart * 20);
        #pragma unroll
        for (int e = 0; e < 5; e++) wv[e] = wp[e];
    };
    auto ldX = [&](int ch) {
        const float* Xc = Xn + (size_t)(ch << 4) * L_;
        #pragma unroll
        for (int r = 0; r < 9; r++) {
            int i = tid + (r << 8);
            if (i < 16 * 132) {
                int ci = i / 132, col = i - ci * 132;
                int gl = l0 + col - 2;
                xv[r] = (gl >= 0 && gl < L_) ? Xc[(size_t)ci * L_ + gl] : 0.f;
            }
        }
    };
    auto stWX = [&](int buf) {
        float4* Wb = Wsm + buf * 80 * 16;
        float*  Xb = Xsm + buf * 16 * 136;
        #pragma unroll
        for (int e = 0; e < 5; e++) {
            const float* f = (const float*)&wv[e];
            #pragma unroll
            for (int j = 0; j < 4; j++)
                ((float*)&Wb[(wPart * 20 + e * 4 + j) * 16 + (wRow >> 2)])[wRow & 3] = f[j];
        }
        #pragma unroll
        for (int r = 0; r < 9; r++) {
            int i = tid + (r << 8);
            if (i < 16 * 132) {
                int ci = i / 132;
                Xb[ci * 136 + (i - ci * 132)] = xv[r];
            }
        }
    };
    auto compute = [&](int buf) {
        const float4* Wb = Wsm + buf * 80 * 16;
        const float*  Xb = Xsm + buf * 16 * 136;
        #pragma unroll
        for (int ci = 0; ci < 16; ci++) {
            const float* row = Xb + ci * 136 + tx * 8;
            float4 q0 = *(const float4*)(row);
            float4 q1 = *(const float4*)(row + 4);
            float4 q2 = *(const float4*)(row + 8);
            float xr[12] = {q0.x,q0.y,q0.z,q0.w, q1.x,q1.y,q1.z,q1.w, q2.x,q2.y,q2.z,q2.w};
            unsigned long long xb[12];
            #pragma unroll
            for (int j = 0; j < 12; j++) xb[j] = bcast2(xr[j]);
            #pragma unroll
            for (int k = 0; k < 5; k++) {
                ulonglong2 wp = *(const ulonglong2*)&Wb[(ci * 5 + k) * 16 + ty];
                #pragma unroll
                for (int jl = 0; jl < 8; jl++) {
                    FMA2(accp[0][jl], wp.x, xb[jl + k]);
                    FMA2(accp[1][jl], wp.y, xb[jl + k]);
                }
            }
        }
    };

    ldW(0); ldX(0); stWX(0);
    __syncthreads();
    #pragma unroll 1
    for (int ch = 0; ch < nCh; ch++) {
        bool more = (ch + 1) < nCh;
        if (more) { ldW(ch + 1); ldX(ch + 1); }
        compute(ch & 1);
        if (more) stWX((ch + 1) & 1);
        __syncthreads();
    }

    #pragma unroll
    for (int p = 0; p < 2; p++) {
        float o[2][8];
        #pragma unroll
        for (int jl = 0; jl < 8; jl++) {
            float2 v = unpack2(accp[p][jl]);
            o[0][jl] = v.x; o[1][jl] = v.y;
        }
        #pragma unroll
        for (int q = 0; q < 2; q++) {
            int co = co0 + ty * 4 + p * 2 + q;
            float bv = bias[co];
            float* op = out + ((size_t)n * CO_ + co) * L_ + l0 + tx * 8;
            *(float4*)(op)     = make_float4(o[q][0]+bv, o[q][1]+bv, o[q][2]+bv, o[q][3]+bv);
            *(float4*)(op + 4) = make_float4(o[q][4]+bv, o[q][5]+bv, o[q][6]+bv, o[q][7]+bv);
        }
    }
}

// ---------------------------------------------------------------------------
__global__ void zero_bar_kernel()
{
    if (threadIdx.x < B_) g_bcnt[threadIdx.x] = 0;
}

// ---------------------------------------------------------------------------
// Persistent weight-resident recurrence: one launch runs all 64 timesteps.
// Grid 32 f-tiles x 8 b = 256 blocks (all co-resident at 2/SM), 256 threads.
// W (4f x 4g x 128ci x 5k = 40KB) loaded into smem ONCE for all steps.
// X double-buffered; stX hoisted BEFORE compute so STS retire under the
// FMA stream (barrier drains nothing). Per-BATCH dependency barrier (32 blocks).
// ---------------------------------------------------------------------------
__global__ __launch_bounds__(256, 2) void lstm_seq_kernel(
    const float* __restrict__ hInit,  // [B, F, L]
    const float* __restrict__ cInit,  // [B, F, L]
    const float* __restrict__ W,      // [CO, CW, 5]
    const float* __restrict__ Ax,     // precomputed input-conv + bias
    size_t axStepStride,              // Ax stride per timestep (floats)
    size_t axStrideB,                 // Ax stride per batch (floats)
    float* __restrict__ cState,       // [B, F, L] running cell state
    float* __restrict__ hOutBase,     // hOut(t) = hOutBase + t*BFL
    int CW, int choff)
{
    float4* Ws = (float4*)dynsmem;                          // [640*4] : [(ci*5+k)*4 + fl]
    float*  Xs = (float*)(dynsmem + 2560 * sizeof(float4)); // [2][16][264]

    const int tid = threadIdx.x;
    const int tx = tid & 63, ty = tid >> 6;
    const int f0 = blockIdx.x * 4;
    const int b  = blockIdx.y;
    const int f  = f0 + ty;
    const int l  = tx * 4;

    // ---- load all weights once (gate-contiguous float4 per (ci,k,f)) ----
    for (int e = tid; e < 2560; e += 256) {
        int row = e >> 2, fl = e & 3;
        int ci = row / 5, k = row - ci * 5;
        int ff = f0 + fl;
        float4 v;
        v.x = W[((size_t)(0 * F_ + ff) * CW + (choff + ci)) * 5 + k];
        v.y = W[((size_t)(1 * F_ + ff) * CW + (choff + ci)) * 5 + k];
        v.z = W[((size_t)(2 * F_ + ff) * CW + (choff + ci)) * 5 + k];
        v.w = W[((size_t)(3 * F_ + ff) * CW + (choff + ci)) * 5 + k];
        Ws[e] = v;
    }

    const size_t BFL = (size_t)B_ * F_ * L_;
    const size_t idx = ((size_t)b * F_ + f) * L_ + l;

    #pragma unroll 1
    for (int t = 0; t < T_; t++) {
        const float* Hb = ((t == 0) ? hInit : hOutBase + (size_t)(t - 1) * BFL)
                          + (size_t)b * F_ * L_;
        const float* Cpv = (t == 0) ? cInit : cState;
        const float* axb = Ax + (size_t)t * axStepStride + (size_t)b * axStrideB
                             + (size_t)f * L_ + l;

        unsigned long long accp[2][4];
        #pragma unroll
        for (int p = 0; p < 2; p++)
            #pragma unroll
            for (int j = 0; j < 4; j++) accp[p][j] = 0ULL;

        float xv[17];
        auto ldX = [&](int ch) {
            const float* Hc = Hb + (size_t)(ch << 4) * L_;
            #pragma unroll
            for (int r = 0; r < 17; r++) {
                int i = tid + (r << 8);
                if (i < 16 * 260) {
                    int ci = i / 260, col = i - ci * 260;
                    int gl = col - 2;
                    xv[r] = (gl >= 0 && gl < L_) ? Hc[(size_t)ci * L_ + gl] : 0.f;
                }
            }
        };
        auto stX = [&](int buf) {
            float* Xb = Xs + buf * 16 * 264;
            #pragma unroll
            for (int r = 0; r < 17; r++) {
                int i = tid + (r << 8);
                if (i < 16 * 260) {
                    int ci = i / 260;
                    Xb[ci * 264 + (i - ci * 260)] = xv[r];
                }
            }
        };
        auto compute = [&](int buf, int ch) {
            const float* Xb = Xs + buf * 16 * 264;
            #pragma unroll
            for (int ci = 0; ci < 16; ci++) {
                const float* row = Xb + ci * 264 + tx * 4;
                float4 q0 = *(const float4*)(row);
                float4 q1 = *(const float4*)(row + 4);
                float xr[8] = {q0.x,q0.y,q0.z,q0.w, q1.x,q1.y,q1.z,q1.w};
                unsigned long long xb[8];
                #pragma unroll
                for (int j = 0; j < 8; j++) xb[j] = bcast2(xr[j]);
                #pragma unroll
                for (int k = 0; k < 5; k++) {
                    ulonglong2 wp = *(const ulonglong2*)&Ws[((((ch << 4) + ci) * 5 + k) << 2) + ty];
                    #pragma unroll
                    for (int jl = 0; jl < 4; jl++) {
                        FMA2(accp[0][jl], wp.x, xb[jl + k]);
                        FMA2(accp[1][jl], wp.y, xb[jl + k]);
                    }
                }
            }
        };

        float4 A0, A1, A2, A3, cp;

        // Prologue: stage chunk 0, start LDG for chunk 1 (overlaps barrier drain).
        ldX(0); stX(0);
        ldX(1);
        __syncthreads();     // also covers the one-time W load on t==0
        #pragma unroll 1
        for (int ch = 0; ch < 8; ch++) {
            // STS for chunk ch+1 issued FIRST — retires under compute(ch).
            if (ch < 7) stX((ch + 1) & 1);
            if (ch < 6) {
                ldX(ch + 2);       // LDG for chunk ch+2, consumed next iteration
            } else if (ch == 7) {
                // epilogue operand prefetch fills the last chunk's slack
                A0 = *(const float4*)(axb + (size_t)0 * F_ * L_);
                A1 = *(const float4*)(axb + (size_t)1 * F_ * L_);
                A2 = *(const float4*)(axb + (size_t)2 * F_ * L_);
                A3 = *(const float4*)(axb + (size_t)3 * F_ * L_);
                cp = *(const float4*)&Cpv[idx];
            }
            compute(ch & 1, ch);
            __syncthreads();
        }

        // ---- epilogue: gates + LSTM update ----
        float acc[4][4];
        #pragma unroll
        for (int p = 0; p < 2; p++)
            #pragma unroll
            for (int jl = 0; jl < 4; jl++) {
                float2 v = unpack2(accp[p][jl]);
                acc[2 * p][jl]     = v.x;
                acc[2 * p + 1][jl] = v.y;
            }

        float Ai[4] = {A0.x+acc[0][0], A0.y+acc[0][1], A0.z+acc[0][2], A0.w+acc[0][3]};
        float Af[4] = {A1.x+acc[1][0], A1.y+acc[1][1], A1.z+acc[1][2], A1.w+acc[1][3]};
        float Ao[4] = {A2.x+acc[2][0], A2.y+acc[2][1], A2.z+acc[2][2], A2.w+acc[2][3]};
        float Ag[4] = {A3.x+acc[3][0], A3.y+acc[3][1], A3.z+acc[3][2], A3.w+acc[3][3]};
        float cpv4[4] = {cp.x, cp.y, cp.z, cp.w};

        float cn[4], hn[4];
        #pragma unroll
        for (int jl = 0; jl < 4; jl++) {
            float ig = sigm(Ai[jl]);
            float fg = sigm(Af[jl]);
            float og = sigm(Ao[jl]);
            float gg = tanh_fast(Ag[jl]);
            cn[jl] = fg * cpv4[jl] + ig * gg;
            hn[jl] = og * tanh_fast(cn[jl]);
        }
        *(float4*)&cState[idx] = make_float4(cn[0], cn[1], cn[2], cn[3]);
        float* ho = hOutBase + (size_t)t * BFL;
        *(float4*)&ho[idx] = make_float4(hn[0], hn[1], hn[2], hn[3]);

        // ---- per-batch barrier (32 blocks of batch b), not after last step ----
        __threadfence();
        __syncthreads();
        if (t < T_ - 1) {
            if (tid == 0) {
                atomicAdd(&g_bcnt[b], 1);
                int target = (t + 1) * 32;
                volatile int* bc = (volatile int*)&g_bcnt[b];
                while (*bc < target) __nanosleep(32);
            }
            __syncthreads();
            __threadfence();
        }
    }
}

// ---------------------------------------------------------------------------
extern "C" void kernel_launch(void* const* d_in, const int* in_sizes, int n_in,
                              void* d_out, int out_size)
{
    const float* x  = (const float*)d_in[0];  // [B, T, Cin, L]
    const float* W0 = (const float*)d_in[1];  // [512, 192, 5]
    const float* b0 = (const float*)d_in[2];  // [512]
    const float* W1 = (const float*)d_in[3];  // [512, 256, 5]
    const float* b1 = (const float*)d_in[4];  // [512]
    const float* h0 = (const float*)d_in[5];  // [B, F, L]
    const float* c0 = (const float*)d_in[6];
    const float* h1 = (const float*)d_in[7];
    const float* c1 = (const float*)d_in[8];
    float* out = (float*)d_out;               // [T, B, F, L]

    cudaFuncSetAttribute(conv_gemm_kernel,
                         cudaFuncAttributeMaxDynamicSharedMemorySize, CONV_SMEM);
    cudaFuncSetAttribute(lstm_seq_kernel,
                         cudaFuncAttributeMaxDynamicSharedMemorySize, SEQ_SMEM);

    float *Ax, *hs0, *c0s, *c1s;
    cudaGetSymbolAddress((void**)&Ax,  g_Ax);
    cudaGetSymbolAddress((void**)&hs0, g_hs0);
    cudaGetSymbolAddress((void**)&c0s, g_c0s);
    cudaGetSymbolAddress((void**)&c1s, g_c1s);

    // Phase 1: Ax0[n=b*T+t] = bias0 + conv(x_t, W0[:, :Cin])
    conv_gemm_kernel<<<dim3(2, 8, 512), 256, CONV_SMEM>>>(x, W0, b0, Ax, CIN_, CIN_ + F_, 0);

    // Phase 2: layer-0 recurrence, one persistent launch (64 steps).
    zero_bar_kernel<<<1, 32>>>();
    lstm_seq_kernel<<<dim3(32, 8), 256, SEQ_SMEM>>>(
        h0, c0, W0,
        Ax, (size_t)CO_ * L_, (size_t)T_ * CO_ * L_,
        c0s, hs0, CIN_ + F_, CIN_);

    // Phase 3: Ax1[n=t*B+b] = bias1 + conv(hs0, W1[:, :F])
    conv_gemm_kernel<<<dim3(2, 8, 512), 256, CONV_SMEM>>>(hs0, W1, b1, Ax, F_, 2 * F_, 0);

    // Phase 4: layer-1 recurrence, writes d_out directly.
    zero_bar_kernel<<<1, 32>>>();
    lstm_seq_kernel<<<dim3(32, 8), 256, SEQ_SMEM>>>(
        h1, c1, W1,
        Ax, (size_t)B_ * CO_ * L_, (size_t)CO_ * L_,
        c1s, out, 2 * F_, F_);
}

// round 13
// speedup vs baseline: 1.0860x; 1.0860x over previous
#include <cuda_runtime.h>
#include <math.h>

#define B_   8
#define T_   64
#define CIN_ 64
#define L_   256
#define F_   128
#define CO_  512   // 4*F
#define RGRID 256  // persistent grid size

// Scratch (device globals — no runtime allocation allowed).
__device__ float g_Ax[(size_t)512 * CO_ * L_];
__device__ float g_hs0[(size_t)T_ * B_ * F_ * L_];
__device__ float g_c0s[(size_t)B_ * F_ * L_];
__device__ float g_c1s[(size_t)B_ * F_ * L_];
__device__ int   g_bar;   // grid barrier counter (zeroed before each persistent launch)

__device__ __forceinline__ float sigm(float x) { return 1.0f / (1.0f + __expf(-x)); }
__device__ __forceinline__ float tanh_fast(float x) { return 2.0f / (1.0f + __expf(-2.0f * x)) - 1.0f; }

__device__ __forceinline__ unsigned long long bcast2(float v) {
    unsigned long long r;
    asm("mov.b64 %0, {%1, %1};" : "=l"(r) : "f"(v));
    return r;
}
__device__ __forceinline__ float2 unpack2(unsigned long long p) {
    float2 r;
    asm("mov.b64 {%0, %1}, %2;" : "=f"(r.x), "=f"(r.y) : "l"(p));
    return r;
}
#define FMA2(acc, w, x) \
    asm("fma.rn.f32x2 %0, %1, %2, %0;" : "+l"(acc) : "l"(w), "l"(x))

extern __shared__ char dynsmem[];
#define CONV_SMEM (2*80*16*16 + 2*16*136*4)           // 58368 B
#define SEQ_SMEM  (2560*16 + 4*16*264*4)              // 40960 + 67584 = 108544 B

// ---------------------------------------------------------------------------
// Parallel precompute conv (unchanged — measured ~99% of FMA2 roofline).
// ---------------------------------------------------------------------------
__global__ __launch_bounds__(256, 2) void conv_gemm_kernel(
    const float* __restrict__ X,     // [NB, Cx, L]
    const float* __restrict__ W,     // [CO, CW, 5]
    const float* __restrict__ bias,  // [CO]
    float* __restrict__ out,         // [NB, CO, L]
    int Cx, int CW, int c0w)
{
    float4* Wsm = (float4*)dynsmem;                              // [2][80][16]
    float*  Xsm = (float*)(dynsmem + 2*80*16*sizeof(float4));    // [2][16][136]

    const int tid = threadIdx.x;
    const int tx = tid & 15, ty = tid >> 4;
    const int l0  = blockIdx.x * 128;
    const int co0 = blockIdx.y * 64;
    const int n   = blockIdx.z;
    const float* Xn = X + (size_t)n * Cx * L_;

    const int wRow = tid >> 2, wPart = tid & 3;
    const int nCh = Cx >> 4;

    unsigned long long accp[2][8];
    #pragma unroll
    for (int p = 0; p < 2; p++)
        #pragma unroll
        for (int j = 0; j < 8; j++) accp[p][j] = 0ULL;

    float4 wv[5];
    float  xv[9];

    auto ldW = [&](int ch) {
        const float4* wp = (const float4*)(W + (size_t)(co0 + wRow) * CW * 5
                                             + (size_t)(c0w + (ch << 4)) * 5 + wPart * 20);
        #pragma unroll
        for (int e = 0; e < 5; e++) wv[e] = wp[e];
    };
    auto ldX = [&](int ch) {
        const float* Xc = Xn + (size_t)(ch << 4) * L_;
        #pragma unroll
        for (int r = 0; r < 9; r++) {
            int i = tid + (r << 8);
            if (i < 16 * 132) {
                int ci = i / 132, col = i - ci * 132;
                int gl = l0 + col - 2;
                xv[r] = (gl >= 0 && gl < L_) ? Xc[(size_t)ci * L_ + gl] : 0.f;
            }
        }
    };
    auto stWX = [&](int buf) {
        float4* Wb = Wsm + buf * 80 * 16;
        float*  Xb = Xsm + buf * 16 * 136;
        #pragma unroll
        for (int e = 0; e < 5; e++) {
            const float* f = (const float*)&wv[e];
            #pragma unroll
            for (int j = 0; j < 4; j++)
                ((float*)&Wb[(wPart * 20 + e * 4 + j) * 16 + (wRow >> 2)])[wRow & 3] = f[j];
        }
        #pragma unroll
        for (int r = 0; r < 9; r++) {
            int i = tid + (r << 8);
            if (i < 16 * 132) {
                int ci = i / 132;
                Xb[ci * 136 + (i - ci * 132)] = xv[r];
            }
        }
    };
    auto compute = [&](int buf) {
        const float4* Wb = Wsm + buf * 80 * 16;
        const float*  Xb = Xsm + buf * 16 * 136;
        #pragma unroll
        for (int ci = 0; ci < 16; ci++) {
            const float* row = Xb + ci * 136 + tx * 8;
            float4 q0 = *(const float4*)(row);
            float4 q1 = *(const float4*)(row + 4);
            float4 q2 = *(const float4*)(row + 8);
            float xr[12] = {q0.x,q0.y,q0.z,q0.w, q1.x,q1.y,q1.z,q1.w, q2.x,q2.y,q2.z,q2.w};
            unsigned long long xb[12];
            #pragma unroll
            for (int j = 0; j < 12; j++) xb[j] = bcast2(xr[j]);
            #pragma unroll
            for (int k = 0; k < 5; k++) {
                ulonglong2 wp = *(const ulonglong2*)&Wb[(ci * 5 + k) * 16 + ty];
                #pragma unroll
                for (int jl = 0; jl < 8; jl++) {
                    FMA2(accp[0][jl], wp.x, xb[jl + k]);
                    FMA2(accp[1][jl], wp.y, xb[jl + k]);
                }
            }
        }
    };

    ldW(0); ldX(0); stWX(0);
    __syncthreads();
    #pragma unroll 1
    for (int ch = 0; ch < nCh; ch++) {
        bool more = (ch + 1) < nCh;
        if (more) { ldW(ch + 1); ldX(ch + 1); }
        compute(ch & 1);
        if (more) stWX((ch + 1) & 1);
        __syncthreads();
    }

    #pragma unroll
    for (int p = 0; p < 2; p++) {
        float o[2][8];
        #pragma unroll
        for (int jl = 0; jl < 8; jl++) {
            float2 v = unpack2(accp[p][jl]);
            o[0][jl] = v.x; o[1][jl] = v.y;
        }
        #pragma unroll
        for (int q = 0; q < 2; q++) {
            int co = co0 + ty * 4 + p * 2 + q;
            float bv = bias[co];
            float* op = out + ((size_t)n * CO_ + co) * L_ + l0 + tx * 8;
            *(float4*)(op)     = make_float4(o[q][0]+bv, o[q][1]+bv, o[q][2]+bv, o[q][3]+bv);
            *(float4*)(op + 4) = make_float4(o[q][4]+bv, o[q][5]+bv, o[q][6]+bv, o[q][7]+bv);
        }
    }
}

// ---------------------------------------------------------------------------
__global__ void zero_bar_kernel() { if (threadIdx.x == 0) g_bar = 0; }

// ---------------------------------------------------------------------------
// Persistent weight-resident recurrence (R9 structure + quad-buffered X).
// Grid 32 f-tiles x 8 b = 256 blocks, 256 threads, 2 blocks/SM.
// W (40KB) loaded into smem ONCE. X quad-buffered in 16-ci chunks; barrier
// once per TWO chunks (4 per step). Global lockstep grid barrier between steps.
// ---------------------------------------------------------------------------
__global__ __launch_bounds__(256, 2) void lstm_seq_kernel(
    const float* __restrict__ hInit,  // [B, F, L]
    const float* __restrict__ cInit,  // [B, F, L]
    const float* __restrict__ W,      // [CO, CW, 5]
    const float* __restrict__ Ax,     // precomputed input-conv + bias
    size_t axStepStride,              // Ax stride per timestep (floats)
    size_t axStrideB,                 // Ax stride per batch (floats)
    float* __restrict__ cState,       // [B, F, L] running cell state
    float* __restrict__ hOutBase,     // hOut(t) = hOutBase + t*BFL
    int CW, int choff)
{
    float4* Ws = (float4*)dynsmem;                          // [640*4] : [(ci*5+k)*4 + fl]
    float*  Xs = (float*)(dynsmem + 2560 * sizeof(float4)); // [4][16][264]

    const int tid = threadIdx.x;
    const int tx = tid & 63, ty = tid >> 6;
    const int f0 = blockIdx.x * 4;
    const int b  = blockIdx.y;
    const int f  = f0 + ty;
    const int l  = tx * 4;

    // ---- load all weights once (gate-contiguous float4 per (ci,k,f)) ----
    for (int e = tid; e < 2560; e += 256) {
        int row = e >> 2, fl = e & 3;
        int ci = row / 5, k = row - ci * 5;
        int ff = f0 + fl;
        float4 v;
        v.x = W[((size_t)(0 * F_ + ff) * CW + (choff + ci)) * 5 + k];
        v.y = W[((size_t)(1 * F_ + ff) * CW + (choff + ci)) * 5 + k];
        v.z = W[((size_t)(2 * F_ + ff) * CW + (choff + ci)) * 5 + k];
        v.w = W[((size_t)(3 * F_ + ff) * CW + (choff + ci)) * 5 + k];
        Ws[e] = v;
    }

    const size_t BFL = (size_t)B_ * F_ * L_;
    const size_t idx = ((size_t)b * F_ + f) * L_ + l;
    volatile int* bar = &g_bar;

    #pragma unroll 1
    for (int t = 0; t < T_; t++) {
        const float* Hb = ((t == 0) ? hInit : hOutBase + (size_t)(t - 1) * BFL)
                          + (size_t)b * F_ * L_;
        const float* Cpv = (t == 0) ? cInit : cState;
        const float* axb = Ax + (size_t)t * axStepStride + (size_t)b * axStrideB
                             + (size_t)f * L_ + l;

        unsigned long long accp[2][4];
        #pragma unroll
        for (int p = 0; p < 2; p++)
            #pragma unroll
            for (int j = 0; j < 4; j++) accp[p][j] = 0ULL;

        float xv[17];
        auto ldX = [&](int ch) {
            const float* Hc = Hb + (size_t)(ch << 4) * L_;
            #pragma unroll
            for (int r = 0; r < 17; r++) {
                int i = tid + (r << 8);
                if (i < 16 * 260) {
                    int ci = i / 260, col = i - ci * 260;
                    int gl = col - 2;
                    xv[r] = (gl >= 0 && gl < L_) ? Hc[(size_t)ci * L_ + gl] : 0.f;
                }
            }
        };
        auto stX = [&](int ch) {
            float* Xb = Xs + (ch & 3) * 16 * 264;
            #pragma unroll
            for (int r = 0; r < 17; r++) {
                int i = tid + (r << 8);
                if (i < 16 * 260) {
                    int ci = i / 260;
                    Xb[ci * 264 + (i - ci * 260)] = xv[r];
                }
            }
        };
        auto compute = [&](int ch) {
            const float* Xb = Xs + (ch & 3) * 16 * 264;
            #pragma unroll
            for (int ci = 0; ci < 16; ci++) {
                const float* row = Xb + ci * 264 + tx * 4;
                float4 q0 = *(const float4*)(row);
                float4 q1 = *(const float4*)(row + 4);
                float xr[8] = {q0.x,q0.y,q0.z,q0.w, q1.x,q1.y,q1.z,q1.w};
                unsigned long long xb[8];
                #pragma unroll
                for (int j = 0; j < 8; j++) xb[j] = bcast2(xr[j]);
                #pragma unroll
                for (int k = 0; k < 5; k++) {
                    ulonglong2 wp = *(const ulonglong2*)&Ws[((((ch << 4) + ci) * 5 + k) << 2) + ty];
                    #pragma unroll
                    for (int jl = 0; jl < 4; jl++) {
                        FMA2(accp[0][jl], wp.x, xb[jl + k]);
                        FMA2(accp[1][jl], wp.y, xb[jl + k]);
                    }
                }
            }
        };

        float4 A0, A1, A2, A3, cp;

        // Prologue: stage chunks 0,1 (first sync also covers W load on t==0;
        // cross-step buffer reuse is protected by the step-end barrier sync).
        ldX(0); stX(0);
        ldX(1); stX(1);
        __syncthreads();
        // Main: 2 chunks per barrier. Writes target buffers (2p+2)&3,(2p+3)&3;
        // reads touch 2p&3,(2p+1)&3 — disjoint.
        #pragma unroll 1
        for (int p = 0; p < 3; p++) {
            const int c0 = 2 * p;
            ldX(c0 + 2);
            compute(c0);
            stX(c0 + 2);
            ldX(c0 + 3);
            compute(c0 + 1);
            stX(c0 + 3);
            __syncthreads();
        }
        // Tail: chunks 6,7 with epilogue operand prefetch overlapped.
        A0 = *(const float4*)(axb + (size_t)0 * F_ * L_);
        A1 = *(const float4*)(axb + (size_t)1 * F_ * L_);
        A2 = *(const float4*)(axb + (size_t)2 * F_ * L_);
        A3 = *(const float4*)(axb + (size_t)3 * F_ * L_);
        cp = *(const float4*)&Cpv[idx];
        compute(6);
        compute(7);

        // ---- epilogue: gates + LSTM update ----
        float acc[4][4];
        #pragma unroll
        for (int p = 0; p < 2; p++)
            #pragma unroll
            for (int jl = 0; jl < 4; jl++) {
                float2 v = unpack2(accp[p][jl]);
                acc[2 * p][jl]     = v.x;
                acc[2 * p + 1][jl] = v.y;
            }

        float Ai[4] = {A0.x+acc[0][0], A0.y+acc[0][1], A0.z+acc[0][2], A0.w+acc[0][3]};
        float Af[4] = {A1.x+acc[1][0], A1.y+acc[1][1], A1.z+acc[1][2], A1.w+acc[1][3]};
        float Ao[4] = {A2.x+acc[2][0], A2.y+acc[2][1], A2.z+acc[2][2], A2.w+acc[2][3]};
        float Ag[4] = {A3.x+acc[3][0], A3.y+acc[3][1], A3.z+acc[3][2], A3.w+acc[3][3]};
        float cpv4[4] = {cp.x, cp.y, cp.z, cp.w};

        float cn[4], hn[4];
        #pragma unroll
        for (int jl = 0; jl < 4; jl++) {
            float ig = sigm(Ai[jl]);
            float fg = sigm(Af[jl]);
            float og = sigm(Ao[jl]);
            float gg = tanh_fast(Ag[jl]);
            cn[jl] = fg * cpv4[jl] + ig * gg;
            hn[jl] = og * tanh_fast(cn[jl]);
        }
        *(float4*)&cState[idx] = make_float4(cn[0], cn[1], cn[2], cn[3]);
        float* ho = hOutBase + (size_t)t * BFL;
        *(float4*)&ho[idx] = make_float4(hn[0], hn[1], hn[2], hn[3]);

        // ---- global lockstep grid barrier (not after the last step) ----
        __threadfence();
        __syncthreads();
        if (t < T_ - 1) {
            if (tid == 0) {
                atomicAdd(&g_bar, 1);
                int target = (t + 1) * RGRID;
                while (*bar < target) __nanosleep(40);
            }
            __syncthreads();
            __threadfence();
        }
    }
}

// ---------------------------------------------------------------------------
extern "C" void kernel_launch(void* const* d_in, const int* in_sizes, int n_in,
                              void* d_out, int out_size)
{
    const float* x  = (const float*)d_in[0];  // [B, T, Cin, L]
    const float* W0 = (const float*)d_in[1];  // [512, 192, 5]
    const float* b0 = (const float*)d_in[2];  // [512]
    const float* W1 = (const float*)d_in[3];  // [512, 256, 5]
    const float* b1 = (const float*)d_in[4];  // [512]
    const float* h0 = (const float*)d_in[5];  // [B, F, L]
    const float* c0 = (const float*)d_in[6];
    const float* h1 = (const float*)d_in[7];
    const float* c1 = (const float*)d_in[8];
    float* out = (float*)d_out;               // [T, B, F, L]

    cudaFuncSetAttribute(conv_gemm_kernel,
                         cudaFuncAttributeMaxDynamicSharedMemorySize, CONV_SMEM);
    cudaFuncSetAttribute(lstm_seq_kernel,
                         cudaFuncAttributeMaxDynamicSharedMemorySize, SEQ_SMEM);

    float *Ax, *hs0, *c0s, *c1s;
    cudaGetSymbolAddress((void**)&Ax,  g_Ax);
    cudaGetSymbolAddress((void**)&hs0, g_hs0);
    cudaGetSymbolAddress((void**)&c0s, g_c0s);
    cudaGetSymbolAddress((void**)&c1s, g_c1s);

    // Phase 1: Ax0[n=b*T+t] = bias0 + conv(x_t, W0[:, :Cin])
    conv_gemm_kernel<<<dim3(2, 8, 512), 256, CONV_SMEM>>>(x, W0, b0, Ax, CIN_, CIN_ + F_, 0);

    // Phase 2: layer-0 recurrence, one persistent launch (64 steps).
    zero_bar_kernel<<<1, 32>>>();
    lstm_seq_kernel<<<dim3(32, 8), 256, SEQ_SMEM>>>(
        h0, c0, W0,
        Ax, (size_t)CO_ * L_, (size_t)T_ * CO_ * L_,
        c0s, hs0, CIN_ + F_, CIN_);

    // Phase 3: Ax1[n=t*B+b] = bias1 + conv(hs0, W1[:, :F])
    conv_gemm_kernel<<<dim3(2, 8, 512), 256, CONV_SMEM>>>(hs0, W1, b1, Ax, F_, 2 * F_, 0);

    // Phase 4: layer-1 recurrence, writes d_out directly.
    zero_bar_kernel<<<1, 32>>>();
    lstm_seq_kernel<<<dim3(32, 8), 256, SEQ_SMEM>>>(
        h1, c1, W1,
        Ax, (size_t)B_ * CO_ * L_, (size_t)CO_ * L_,
        c1s, out, 2 * F_, F_);
}

// round 14
// speedup vs baseline: 1.0897x; 1.0034x over previous
#include <cuda_runtime.h>
#include <math.h>

#define B_   8
#define T_   64
#define CIN_ 64
#define L_   256
#define F_   128
#define CO_  512   // 4*F

// Scratch (device globals — no runtime allocation allowed).
__device__ float g_Ax[(size_t)512 * CO_ * L_];
__device__ float g_hs0[(size_t)T_ * B_ * F_ * L_];
__device__ float g_c0s[(size_t)B_ * F_ * L_];
__device__ float g_c1s[(size_t)B_ * F_ * L_];
__device__ int   g_bcnt[B_];   // per-batch arrival counters (zeroed before each persistent launch)

__device__ __forceinline__ float sigm(float x) { return 1.0f / (1.0f + __expf(-x)); }
__device__ __forceinline__ float tanh_fast(float x) { return 2.0f / (1.0f + __expf(-2.0f * x)) - 1.0f; }

__device__ __forceinline__ unsigned long long bcast2(float v) {
    unsigned long long r;
    asm("mov.b64 %0, {%1, %1};" : "=l"(r) : "f"(v));
    return r;
}
__device__ __forceinline__ float2 unpack2(unsigned long long p) {
    float2 r;
    asm("mov.b64 {%0, %1}, %2;" : "=f"(r.x), "=f"(r.y) : "l"(p));
    return r;
}
#define FMA2(acc, w, x) \
    asm("fma.rn.f32x2 %0, %1, %2, %0;" : "+l"(acc) : "l"(w), "l"(x))

extern __shared__ char dynsmem[];
#define CONV_SMEM (2*80*16*16 + 2*16*136*4)           // 58368 B
#define SEQ_SMEM  (2560*16 + 4*16*264*4)              // 40960 + 67584 = 108544 B

// ---------------------------------------------------------------------------
// Parallel precompute conv (unchanged — near FMA2 roofline).
// ---------------------------------------------------------------------------
__global__ __launch_bounds__(256, 2) void conv_gemm_kernel(
    const float* __restrict__ X,     // [NB, Cx, L]
    const float* __restrict__ W,     // [CO, CW, 5]
    const float* __restrict__ bias,  // [CO]
    float* __restrict__ out,         // [NB, CO, L]
    int Cx, int CW, int c0w)
{
    float4* Wsm = (float4*)dynsmem;                              // [2][80][16]
    float*  Xsm = (float*)(dynsmem + 2*80*16*sizeof(float4));    // [2][16][136]

    const int tid = threadIdx.x;
    const int tx = tid & 15, ty = tid >> 4;
    const int l0  = blockIdx.x * 128;
    const int co0 = blockIdx.y * 64;
    const int n   = blockIdx.z;
    const float* Xn = X + (size_t)n * Cx * L_;

    const int wRow = tid >> 2, wPart = tid & 3;
    const int nCh = Cx >> 4;

    unsigned long long accp[2][8];
    #pragma unroll
    for (int p = 0; p < 2; p++)
        #pragma unroll
        for (int j = 0; j < 8; j++) accp[p][j] = 0ULL;

    float4 wv[5];
    float  xv[9];

    auto ldW = [&](int ch) {
        const float4* wp = (const float4*)(W + (size_t)(co0 + wRow) * CW * 5
                                             + (size_t)(c0w + (ch << 4)) * 5 + wPart * 20);
        #pragma unroll
        for (int e = 0; e < 5; e++) wv[e] = wp[e];
    };
    auto ldX = [&](int ch) {
        const float* Xc = Xn + (size_t)(ch << 4) * L_;
        #pragma unroll
        for (int r = 0; r < 9; r++) {
            int i = tid + (r << 8);
            if (i < 16 * 132) {
                int ci = i / 132, col = i - ci * 132;
                int gl = l0 + col - 2;
                xv[r] = (gl >= 0 && gl < L_) ? Xc[(size_t)ci * L_ + gl] : 0.f;
            }
        }
    };
    auto stWX = [&](int buf) {
        float4* Wb = Wsm + buf * 80 * 16;
        float*  Xb = Xsm + buf * 16 * 136;
        #pragma unroll
        for (int e = 0; e < 5; e++) {
            const float* f = (const float*)&wv[e];
            #pragma unroll
            for (int j = 0; j < 4; j++)
                ((float*)&Wb[(wPart * 20 + e * 4 + j) * 16 + (wRow >> 2)])[wRow & 3] = f[j];
        }
        #pragma unroll
        for (int r = 0; r < 9; r++) {
            int i = tid + (r << 8);
            if (i < 16 * 132) {
                int ci = i / 132;
                Xb[ci * 136 + (i - ci * 132)] = xv[r];
            }
        }
    };
    auto compute = [&](int buf) {
        const float4* Wb = Wsm + buf * 80 * 16;
        const float*  Xb = Xsm + buf * 16 * 136;
        #pragma unroll
        for (int ci = 0; ci < 16; ci++) {
            const float* row = Xb + ci * 136 + tx * 8;
            float4 q0 = *(const float4*)(row);
            float4 q1 = *(const float4*)(row + 4);
            float4 q2 = *(const float4*)(row + 8);
            float xr[12] = {q0.x,q0.y,q0.z,q0.w, q1.x,q1.y,q1.z,q1.w, q2.x,q2.y,q2.z,q2.w};
            unsigned long long xb[12];
            #pragma unroll
            for (int j = 0; j < 12; j++) xb[j] = bcast2(xr[j]);
            #pragma unroll
            for (int k = 0; k < 5; k++) {
                ulonglong2 wp = *(const ulonglong2*)&Wb[(ci * 5 + k) * 16 + ty];
                #pragma unroll
                for (int jl = 0; jl < 8; jl++) {
                    FMA2(accp[0][jl], wp.x, xb[jl + k]);
                    FMA2(accp[1][jl], wp.y, xb[jl + k]);
                }
            }
        }
    };

    ldW(0); ldX(0); stWX(0);
    __syncthreads();
    #pragma unroll 1
    for (int ch = 0; ch < nCh; ch++) {
        bool more = (ch + 1) < nCh;
        if (more) { ldW(ch + 1); ldX(ch + 1); }
        compute(ch & 1);
        if (more) stWX((ch + 1) & 1);
        __syncthreads();
    }

    #pragma unroll
    for (int p = 0; p < 2; p++) {
        float o[2][8];
        #pragma unroll
        for (int jl = 0; jl < 8; jl++) {
            float2 v = unpack2(accp[p][jl]);
            o[0][jl] = v.x; o[1][jl] = v.y;
        }
        #pragma unroll
        for (int q = 0; q < 2; q++) {
            int co = co0 + ty * 4 + p * 2 + q;
            float bv = bias[co];
            float* op = out + ((size_t)n * CO_ + co) * L_ + l0 + tx * 8;
            *(float4*)(op)     = make_float4(o[q][0]+bv, o[q][1]+bv, o[q][2]+bv, o[q][3]+bv);
            *(float4*)(op + 4) = make_float4(o[q][4]+bv, o[q][5]+bv, o[q][6]+bv, o[q][7]+bv);
        }
    }
}

// ---------------------------------------------------------------------------
__global__ void zero_bar_kernel() { if (threadIdx.x < B_) g_bcnt[threadIdx.x] = 0; }

// ---------------------------------------------------------------------------
// Persistent weight-resident recurrence (R13 structure; barrier arrivals split
// across 8 per-batch counters, GLOBAL lockstep wait semantics preserved).
// Grid 32 f-tiles x 8 b = 256 blocks, 256 threads, 2 blocks/SM.
// W (40KB) loaded into smem ONCE. X quad-buffered in 16-ci chunks; barrier
// once per TWO chunks (4 per step). Grid barrier between steps.
// ---------------------------------------------------------------------------
__global__ __launch_bounds__(256, 2) void lstm_seq_kernel(
    const float* __restrict__ hInit,  // [B, F, L]
    const float* __restrict__ cInit,  // [B, F, L]
    const float* __restrict__ W,      // [CO, CW, 5]
    const float* __restrict__ Ax,     // precomputed input-conv + bias
    size_t axStepStride,              // Ax stride per timestep (floats)
    size_t axStrideB,                 // Ax stride per batch (floats)
    float* __restrict__ cState,       // [B, F, L] running cell state
    float* __restrict__ hOutBase,     // hOut(t) = hOutBase + t*BFL
    int CW, int choff)
{
    float4* Ws = (float4*)dynsmem;                          // [640*4] : [(ci*5+k)*4 + fl]
    float*  Xs = (float*)(dynsmem + 2560 * sizeof(float4)); // [4][16][264]

    const int tid = threadIdx.x;
    const int tx = tid & 63, ty = tid >> 6;
    const int f0 = blockIdx.x * 4;
    const int b  = blockIdx.y;
    const int f  = f0 + ty;
    const int l  = tx * 4;

    // ---- load all weights once (gate-contiguous float4 per (ci,k,f)) ----
    for (int e = tid; e < 2560; e += 256) {
        int row = e >> 2, fl = e & 3;
        int ci = row / 5, k = row - ci * 5;
        int ff = f0 + fl;
        float4 v;
        v.x = W[((size_t)(0 * F_ + ff) * CW + (choff + ci)) * 5 + k];
        v.y = W[((size_t)(1 * F_ + ff) * CW + (choff + ci)) * 5 + k];
        v.z = W[((size_t)(2 * F_ + ff) * CW + (choff + ci)) * 5 + k];
        v.w = W[((size_t)(3 * F_ + ff) * CW + (choff + ci)) * 5 + k];
        Ws[e] = v;
    }

    const size_t BFL = (size_t)B_ * F_ * L_;
    const size_t idx = ((size_t)b * F_ + f) * L_ + l;

    #pragma unroll 1
    for (int t = 0; t < T_; t++) {
        const float* Hb = ((t == 0) ? hInit : hOutBase + (size_t)(t - 1) * BFL)
                          + (size_t)b * F_ * L_;
        const float* Cpv = (t == 0) ? cInit : cState;
        const float* axb = Ax + (size_t)t * axStepStride + (size_t)b * axStrideB
                             + (size_t)f * L_ + l;

        unsigned long long accp[2][4];
        #pragma unroll
        for (int p = 0; p < 2; p++)
            #pragma unroll
            for (int j = 0; j < 4; j++) accp[p][j] = 0ULL;

        float xv[17];
        auto ldX = [&](int ch) {
            const float* Hc = Hb + (size_t)(ch << 4) * L_;
            #pragma unroll
            for (int r = 0; r < 17; r++) {
                int i = tid + (r << 8);
                if (i < 16 * 260) {
                    int ci = i / 260, col = i - ci * 260;
                    int gl = col - 2;
                    xv[r] = (gl >= 0 && gl < L_) ? Hc[(size_t)ci * L_ + gl] : 0.f;
                }
            }
        };
        auto stX = [&](int ch) {
            float* Xb = Xs + (ch & 3) * 16 * 264;
            #pragma unroll
            for (int r = 0; r < 17; r++) {
                int i = tid + (r << 8);
                if (i < 16 * 260) {
                    int ci = i / 260;
                    Xb[ci * 264 + (i - ci * 260)] = xv[r];
                }
            }
        };
        auto compute = [&](int ch) {
            const float* Xb = Xs + (ch & 3) * 16 * 264;
            #pragma unroll
            for (int ci = 0; ci < 16; ci++) {
                const float* row = Xb + ci * 264 + tx * 4;
                float4 q0 = *(const float4*)(row);
                float4 q1 = *(const float4*)(row + 4);
                float xr[8] = {q0.x,q0.y,q0.z,q0.w, q1.x,q1.y,q1.z,q1.w};
                unsigned long long xb[8];
                #pragma unroll
                for (int j = 0; j < 8; j++) xb[j] = bcast2(xr[j]);
                #pragma unroll
                for (int k = 0; k < 5; k++) {
                    ulonglong2 wp = *(const ulonglong2*)&Ws[((((ch << 4) + ci) * 5 + k) << 2) + ty];
                    #pragma unroll
                    for (int jl = 0; jl < 4; jl++) {
                        FMA2(accp[0][jl], wp.x, xb[jl + k]);
                        FMA2(accp[1][jl], wp.y, xb[jl + k]);
                    }
                }
            }
        };

        float4 A0, A1, A2, A3, cp;

        // Prologue: stage chunks 0,1 (first sync also covers W load on t==0;
        // cross-step buffer reuse is protected by the step-end barrier sync).
        ldX(0); stX(0);
        ldX(1); stX(1);
        __syncthreads();
        // Main: 2 chunks per barrier. Writes target buffers (2p+2)&3,(2p+3)&3;
        // reads touch 2p&3,(2p+1)&3 — disjoint.
        #pragma unroll 1
        for (int p = 0; p < 3; p++) {
            const int c0 = 2 * p;
            ldX(c0 + 2);
            compute(c0);
            stX(c0 + 2);
            ldX(c0 + 3);
            compute(c0 + 1);
            stX(c0 + 3);
            __syncthreads();
        }
        // Tail: chunks 6,7 with epilogue operand prefetch overlapped.
        A0 = *(const float4*)(axb + (size_t)0 * F_ * L_);
        A1 = *(const float4*)(axb + (size_t)1 * F_ * L_);
        A2 = *(const float4*)(axb + (size_t)2 * F_ * L_);
        A3 = *(const float4*)(axb + (size_t)3 * F_ * L_);
        cp = *(const float4*)&Cpv[idx];
        compute(6);
        compute(7);

        // ---- epilogue: gates + LSTM update ----
        float acc[4][4];
        #pragma unroll
        for (int p = 0; p < 2; p++)
            #pragma unroll
            for (int jl = 0; jl < 4; jl++) {
                float2 v = unpack2(accp[p][jl]);
                acc[2 * p][jl]     = v.x;
                acc[2 * p + 1][jl] = v.y;
            }

        float Ai[4] = {A0.x+acc[0][0], A0.y+acc[0][1], A0.z+acc[0][2], A0.w+acc[0][3]};
        float Af[4] = {A1.x+acc[1][0], A1.y+acc[1][1], A1.z+acc[1][2], A1.w+acc[1][3]};
        float Ao[4] = {A2.x+acc[2][0], A2.y+acc[2][1], A2.z+acc[2][2], A2.w+acc[2][3]};
        float Ag[4] = {A3.x+acc[3][0], A3.y+acc[3][1], A3.z+acc[3][2], A3.w+acc[3][3]};
        float cpv4[4] = {cp.x, cp.y, cp.z, cp.w};

        float cn[4], hn[4];
        #pragma unroll
        for (int jl = 0; jl < 4; jl++) {
            float ig = sigm(Ai[jl]);
            float fg = sigm(Af[jl]);
            float og = sigm(Ao[jl]);
            float gg = tanh_fast(Ag[jl]);
            cn[jl] = fg * cpv4[jl] + ig * gg;
            hn[jl] = og * tanh_fast(cn[jl]);
        }
        *(float4*)&cState[idx] = make_float4(cn[0], cn[1], cn[2], cn[3]);
        float* ho = hOutBase + (size_t)t * BFL;
        *(float4*)&ho[idx] = make_float4(hn[0], hn[1], hn[2], hn[3]);

        // ---- lockstep grid barrier with parallel arrivals/detection ----
        // Arrivals spread across 8 per-batch counters (32 same-address atomics
        // each instead of 256 -> ~8x less L2-atomic serialization). Wait
        // semantics remain GLOBAL: threads 0..7 each poll one counter until
        // ALL batches completed step t (phase-aligned like R9/R13).
        __threadfence();
        __syncthreads();
        if (t < T_ - 1) {
            if (tid == 0) atomicAdd(&g_bcnt[b], 1);
            if (tid < B_) {
                const int target = (t + 1) * 32;
                volatile int* bc = (volatile int*)&g_bcnt[tid];
                while (*bc < target) __nanosleep(40);
            }
            __syncthreads();
            __threadfence();
        }
    }
}

// ---------------------------------------------------------------------------
extern "C" void kernel_launch(void* const* d_in, const int* in_sizes, int n_in,
                              void* d_out, int out_size)
{
    const float* x  = (const float*)d_in[0];  // [B, T, Cin, L]
    const float* W0 = (const float*)d_in[1];  // [512, 192, 5]
    const float* b0 = (const float*)d_in[2];  // [512]
    const float* W1 = (const float*)d_in[3];  // [512, 256, 5]
    const float* b1 = (const float*)d_in[4];  // [512]
    const float* h0 = (const float*)d_in[5];  // [B, F, L]
    const float* c0 = (const float*)d_in[6];
    const float* h1 = (const float*)d_in[7];
    const float* c1 = (const float*)d_in[8];
    float* out = (float*)d_out;               // [T, B, F, L]

    cudaFuncSetAttribute(conv_gemm_kernel,
                         cudaFuncAttributeMaxDynamicSharedMemorySize, CONV_SMEM);
    cudaFuncSetAttribute(lstm_seq_kernel,
                         cudaFuncAttributeMaxDynamicSharedMemorySize, SEQ_SMEM);

    float *Ax, *hs0, *c0s, *c1s;
    cudaGetSymbolAddress((void**)&Ax,  g_Ax);
    cudaGetSymbolAddress((void**)&hs0, g_hs0);
    cudaGetSymbolAddress((void**)&c0s, g_c0s);
    cudaGetSymbolAddress((void**)&c1s, g_c1s);

    // Phase 1: Ax0[n=b*T+t] = bias0 + conv(x_t, W0[:, :Cin])
    conv_gemm_kernel<<<dim3(2, 8, 512), 256, CONV_SMEM>>>(x, W0, b0, Ax, CIN_, CIN_ + F_, 0);

    // Phase 2: layer-0 recurrence, one persistent launch (64 steps).
    zero_bar_kernel<<<1, 32>>>();
    lstm_seq_kernel<<<dim3(32, 8), 256, SEQ_SMEM>>>(
        h0, c0, W0,
        Ax, (size_t)CO_ * L_, (size_t)T_ * CO_ * L_,
        c0s, hs0, CIN_ + F_, CIN_);

    // Phase 3: Ax1[n=t*B+b] = bias1 + conv(hs0, W1[:, :F])
    conv_gemm_kernel<<<dim3(2, 8, 512), 256, CONV_SMEM>>>(hs0, W1, b1, Ax, F_, 2 * F_, 0);

    // Phase 4: layer-1 recurrence, writes d_out directly.
    zero_bar_kernel<<<1, 32>>>();
    lstm_seq_kernel<<<dim3(32, 8), 256, SEQ_SMEM>>>(
        h1, c1, W1,
        Ax, (size_t)B_ * CO_ * L_, (size_t)CO_ * L_,
        c1s, out, 2 * F_, F_);
}